// round 6
// baseline (speedup 1.0000x reference)
#include <cuda_runtime.h>
#include <math.h>

#define F_BINS   4096
#define W_HALF   256
#define TAPS     (2*W_HALF)            // 512
#define NBUF_LEN (F_BINS + 2*W_HALF)   // 4608
#define NCH      48
#define NCT      96
#define NSLICE   4
#define NCTA     (NCT*NSLICE)          // 384
#define HW_IN    (512*512)
#define BROWS    16
#define HROWS    (2*BROWS + 2)         // 34
#define USTEP    0.0732421875f         // 300/4096

// scratch (static device globals -- zero-initialized at module load; winner re-zeroes each launch)
__device__ __align__(16) float g_T[NCT * 257];
__device__ int g_done_all;

#define K1_SMEM (F_BINS*4 + HROWS*256*4)   // 16384 + 34816 = 51200

__global__ void __launch_bounds__(512) k_all(const float* __restrict__ pred,
                                             const float* __restrict__ tgt,
                                             float* __restrict__ out) {
    extern __shared__ unsigned char smraw[];
    unsigned int* sh_hist = reinterpret_cast<unsigned int*>(smraw);          // [4096] phase A
    float* sh_h = reinterpret_cast<float*>(smraw + F_BINS*4);                // [34][256] phase A
    __shared__ float csuf[257];
    __shared__ float chunk[256];
    __shared__ int s_ticket;
    __shared__ float s_red[16];

    const int ct    = blockIdx.x;   // 0..95
    const int slice = blockIdx.y;   // 0..3
    const int tid   = threadIdx.x;
    const int warp  = tid >> 5, lane = tid & 31;
    const unsigned FULL = 0xffffffffu;

    const int r0 = slice * 64;
    const int r1 = r0 + 64;

    const float* src = (ct < NCH) ? (pred + (size_t)ct * HW_IN)
                                  : (tgt  + (size_t)(ct - NCH) * HW_IN);

    // ================= Phase A: resize + private slice histogram =================
    for (int i = tid; i < F_BINS; i += 512) sh_hist[i] = 0u;
    __syncthreads();

    for (int oyb = r0; oyb < r1; oyb += BROWS) {
        for (int lr = warp; lr < HROWS; lr += 16) {
            int iy = 2*oyb - 1 + lr;
            iy = iy < 0 ? 0 : (iy > 511 ? 511 : iy);
            const float4* row4 = reinterpret_cast<const float4*>(src + (size_t)iy * 512);
            float4 v0 = row4[lane];
            float4 v1 = row4[32 + lane];
            float4 v2 = row4[64 + lane];
            float4 v3 = row4[96 + lane];
            float cl1 = __shfl_sync(FULL, v0.w, 31);
            float cl2 = __shfl_sync(FULL, v1.w, 31);
            float cl3 = __shfl_sync(FULL, v2.w, 31);
            float cr0 = __shfl_sync(FULL, v1.x, 0);
            float cr1 = __shfl_sync(FULL, v2.x, 0);
            float cr2 = __shfl_sync(FULL, v3.x, 0);
            float carryL[4] = {0.f, cl1, cl2, cl3};
            float carryR[4] = {cr0, cr1, cr2, 0.f};
            float4 vv[4] = {v0, v1, v2, v3};
            float2* hd = reinterpret_cast<float2*>(sh_h + lr*256);
            #pragma unroll
            for (int c = 0; c < 4; c++) {
                float4 v = vv[c];
                float left  = __shfl_up_sync(FULL, v.w, 1);
                if (lane == 0)  left  = carryL[c];
                float right = __shfl_down_sync(FULL, v.x, 1);
                if (lane == 31) right = carryR[c];
                float ha, hb;
                if (c == 0 && lane == 0)
                    ha = (3.f*v.x + 3.f*v.y + v.z) * (1.f/7.f);
                else
                    ha = (left + 3.f*v.x + 3.f*v.y + v.z) * 0.125f;
                if (c == 3 && lane == 31)
                    hb = (v.y + 3.f*v.z + 3.f*v.w) * (1.f/7.f);
                else
                    hb = (v.y + 3.f*v.z + 3.f*v.w + right) * 0.125f;
                hd[c*32 + lane] = make_float2(ha, hb);
            }
        }
        __syncthreads();

        for (int p = tid; p < BROWS*256; p += 512) {
            int oyl = p >> 8;
            int ox  = p & 255;
            int oy  = oyb + oyl;
            const float* hp = sh_h + (2*oyl)*256 + ox;
            float a0 = hp[0], a1 = hp[256], a2 = hp[512], a3 = hp[768];
            float inv = (oy == 0 || oy == 255) ? (1.f/7.f) : 0.125f;
            float w0 = (oy == 0)   ? 0.f : inv;
            float w3 = (oy == 255) ? 0.f : inv;
            float val = w0*a0 + 3.f*inv*(a1 + a2) + w3*a3;
            int bin = (int)(val * (float)F_BINS);
            bin = bin < 0 ? 0 : (bin > F_BINS-1 ? F_BINS-1 : bin);
            atomicAdd(&sh_hist[bin], 1u);
        }
        __syncthreads();
    }

    // ================= Phase B (per-CTA): partial T(m) from OWN slice hist =================
    // nbuf/tab live in the sh_h region; sh_hist stays intact while we copy from it.
    float* nbuf = reinterpret_cast<float*>(smraw + F_BINS*4);   // [4608]
    float* tab  = nbuf + NBUF_LEN;                              // [512]

    if (tid < W_HALF) {
        nbuf[tid] = 0.f;
        nbuf[W_HALF + F_BINS + tid] = 0.f;
    }
    if (tid < TAPS)
        tab[tid] = 1.f / (1.f + expf(-USTEP * ((float)tid - 255.5f)));
    __syncthreads();
    for (int k = tid; k < F_BINS; k += 512)
        nbuf[W_HALF + k] = (float)sh_hist[k];
    __syncthreads();

    // 16-bin chunk sums (one per coarse bin)
    if (tid < 256) {
        const float4* p4 = reinterpret_cast<const float4*>(nbuf + W_HALF) + tid*4;
        float4 v0 = p4[0], v1 = p4[1], v2 = p4[2], v3 = p4[3];
        chunk[tid] = (v0.x+v0.y+v0.z+v0.w) + (v1.x+v1.y+v1.z+v1.w)
                   + (v2.x+v2.y+v2.z+v2.w) + (v3.x+v3.y+v3.z+v3.w);
    }
    __syncthreads();
    if (tid < 32) {      // suffix scan of 256 chunks
        float loc[8];
        float run = 0.f;
        #pragma unroll
        for (int i = 7; i >= 0; i--) { run += chunk[tid*8 + i]; loc[i] = run; }
        float t_l = run, suf = run;
        #pragma unroll
        for (int off = 1; off < 32; off <<= 1) {
            float v = __shfl_down_sync(FULL, suf, off);
            if (tid + off < 32) suf += v;
        }
        float above = suf - t_l;
        #pragma unroll
        for (int i = 0; i < 8; i++) csuf[tid*8 + i] = loc[i] + above;
        if (tid == 0) csuf[256] = 0.f;
    }
    __syncthreads();

    const float4* nb4 = reinterpret_cast<const float4*>(nbuf);
    const float4* tb4 = reinterpret_cast<const float4*>(tab);
    for (int m = warp; m <= 256; m += 16) {
        const float4* base = nb4 + m*4;      // window starts at fine bin 16m-256
        float acc = 0.f;
        #pragma unroll
        for (int q = 0; q < 4; q++) {
            float4 x  = base[q*32 + lane];
            float4 tq = tb4[q*32 + lane];
            acc += x.x*tq.x + x.y*tq.y + x.z*tq.z + x.w*tq.w;
        }
        #pragma unroll
        for (int off = 16; off; off >>= 1)
            acc += __shfl_down_sync(FULL, acc, off);
        if (lane == 0) {
            int cc = m + 16;
            float S = (cc < 256) ? csuf[cc] : 0.f;
            atomicAdd(&g_T[ct*257 + m], S + acc);
        }
    }

    // ================= Ticket: last CTA of the whole grid does the reduction =================
    __syncthreads();
    __threadfence();
    if (tid == 0) s_ticket = atomicAdd(&g_done_all, 1);
    __syncthreads();
    if (s_ticket != NCTA - 1) return;
    if (tid == 0) atomicExch(&g_done_all, 0);   // self-reset for next replay

    // ================= Phase C: CDF L1 reduction =================
    float s = 0.f;
    for (int e = tid; e < NCH*256; e += 512) {
        int p  = e >> 8;
        int bb = e & 255;
        const float* Tp = g_T + p*257;
        const float* Tt = g_T + (NCH + p)*257;
        float p0 = __ldcg(&Tp[0]), t0 = __ldcg(&Tt[0]);
        float pe = __ldcg(&Tp[256]), te = __ldcg(&Tt[256]);
        float invp = 1.f / (p0 - pe);
        float invt = 1.f / (t0 - te);
        float cp  = (p0 - __ldcg(&Tp[bb+1])) * invp;
        float ctv = (t0 - __ldcg(&Tt[bb+1])) * invt;
        s += fabsf(cp - ctv);
    }
    #pragma unroll
    for (int off = 16; off; off >>= 1) s += __shfl_down_sync(FULL, s, off);
    if (lane == 0) s_red[warp] = s;
    __syncthreads();
    if (tid < 32) {
        float v = (tid < 16) ? s_red[tid] : 0.f;
        #pragma unroll
        for (int off = 16; off; off >>= 1) v += __shfl_down_sync(FULL, v, off);
        if (tid == 0) out[0] = v * (1.0f / (48.0f * 256.0f));
    }
    __syncthreads();
    // zero g_T for the next graph replay (values already consumed above)
    for (int i = tid; i < NCT*257; i += 512) g_T[i] = 0.f;
}

extern "C" void kernel_launch(void* const* d_in, const int* in_sizes, int n_in,
                              void* d_out, int out_size) {
    const float* pred = (const float*)d_in[0];
    const float* tgt  = (const float*)d_in[1];
    float* out = (float*)d_out;

    cudaFuncSetAttribute(k_all, cudaFuncAttributeMaxDynamicSharedMemorySize, K1_SMEM);
    k_all<<<dim3(NCT, NSLICE), 512, K1_SMEM>>>(pred, tgt, out);
}